// round 9
// baseline (speedup 1.0000x reference)
#include <cuda_runtime.h>
#include <math.h>
#include <stdint.h>

#define NB 8
#define NH 16
#define ND 64
#define NS 1024
#define NE 1024
#define NHB 128   // NH*NB

// ---- scratch (device globals; no allocations allowed) ----
__device__ float g_pe[NS * NE];         // (L,E) positional encoding table
__device__ float g_xh[NHB * NS * ND];   // (h,b,s,d) with pos-enc, fp32 (residual)
__device__ float g_q [NHB * NS * ND];
__device__ float g_k [NHB * NS * ND];
__device__ float g_v [NHB * NS * ND];
__device__ float g_y [NB * NS * NE];    // (b,s,e) pre-layernorm
__device__ float g_mu  [NB * NS];
__device__ float g_rstd[NB * NS];

// ---------------------------------------------------------------------------
// helpers
// ---------------------------------------------------------------------------
__device__ __forceinline__ float tf32r(float f) {
    uint32_t u;
    asm("cvt.rna.tf32.f32 %0, %1;" : "=r"(u) : "f"(f));
    return __uint_as_float(u);
}
__device__ __forceinline__ float tanh_fast(float x) {
    float y;
    asm("tanh.approx.f32 %0, %1;" : "=f"(y) : "f"(x));
    return y;
}
// D += A(16x8) * B(8x8), tf32 inputs, fp32 accum
__device__ __forceinline__ void mma8(float4& d, const uint32_t a[4],
                                     uint32_t b0, uint32_t b1) {
    asm("mma.sync.aligned.m16n8k8.row.col.f32.tf32.tf32.f32 "
        "{%0,%1,%2,%3}, {%4,%5,%6,%7}, {%8,%9}, {%0,%1,%2,%3};"
        : "+f"(d.x), "+f"(d.y), "+f"(d.z), "+f"(d.w)
        : "r"(a[0]), "r"(a[1]), "r"(a[2]), "r"(a[3]), "r"(b0), "r"(b1));
}
__device__ __forceinline__ void cpa16(uint32_t smem_addr, const void* gptr) {
    asm volatile("cp.async.cg.shared.global [%0], [%1], 16;"
                 :: "r"(smem_addr), "l"(gptr));
}
#define CPA_COMMIT() asm volatile("cp.async.commit_group;")
#define U(x) __float_as_uint(x)

// ============================================================================
// Kernel 0: precompute (L,E) pos-enc table. One thread per (sin,cos) pair.
// ============================================================================
__global__ void pe_kernel()
{
    const int i = blockIdx.x * blockDim.x + threadIdx.x;   // 0 .. 524287
    const int l = i >> 9;          // row (position)
    const int e = (i & 511) * 2;   // even column
    const float ln_factor = 0.0089944730195079f;   // log(10000)/1024
    float dv  = expf(-(float)e * ln_factor);
    float ang = (float)l * dv;
    float s, c;
    sincosf(ang, &s, &c);
    *(float2*)&g_pe[l * NE + e] = make_float2(s, c);
}

// ============================================================================
// Kernel 1: xh = reshape(x)+pe ; q/k/v = per-head 2-layer tanh MLP (tf32 mma)
// Block: one (h,b) x 128 s-rows. 8 warps = 4(M) x 2(N); 2 row-blocks/warp.
// ============================================================================
__device__ __forceinline__ void mma_layer(
    const float* As,                 // smem [128][68], tf32 values
    const float* __restrict__ Wg,    // global [64][64] (k=d_in, n=d_out)
    const float* __restrict__ bg,    // global [64]
    float* Ws, float* bs,            // smem staging [64][72], [64]
    float* outS,                     // smem [128][68] (tf32) or nullptr
    float* outG,                     // global (row stride 64) or nullptr
    int wm, int wn, int g, int tig, int tid)
{
    __syncthreads();   // prior consumers of Ws / producers of As done
    for (int i = tid; i < 1024; i += 256) {
        int r = i >> 4, c = (i & 15) * 4;
        float4 wv = *(const float4*)&Wg[r * 64 + c];
        wv.x = tf32r(wv.x); wv.y = tf32r(wv.y);
        wv.z = tf32r(wv.z); wv.w = tf32r(wv.w);
        *(float4*)&Ws[r * 72 + c] = wv;
    }
    if (tid < 64) bs[tid] = bg[tid];
    __syncthreads();

    float4 acc[2][4];
#pragma unroll
    for (int mb = 0; mb < 2; mb++)
#pragma unroll
        for (int j = 0; j < 4; j++) acc[mb][j] = make_float4(0.f, 0.f, 0.f, 0.f);

#pragma unroll
    for (int kk = 0; kk < 8; kk++) {
        const int c = 8 * kk + tig;
        uint32_t a[2][4];
#pragma unroll
        for (int mb = 0; mb < 2; mb++) {
            const int ra = 32 * wm + 16 * mb + g;
            a[mb][0] = U(As[ra * 68 + c]);
            a[mb][1] = U(As[(ra + 8) * 68 + c]);
            a[mb][2] = U(As[ra * 68 + c + 4]);
            a[mb][3] = U(As[(ra + 8) * 68 + c + 4]);
        }
#pragma unroll
        for (int j = 0; j < 4; j++) {
            const int n = 32 * wn + 8 * j + g;
            uint32_t b0 = U(Ws[(8 * kk + tig) * 72 + n]);
            uint32_t b1 = U(Ws[(8 * kk + tig + 4) * 72 + n]);
            mma8(acc[0][j], a[0], b0, b1);
            mma8(acc[1][j], a[1], b0, b1);
        }
    }
    // bias + tanh + store
#pragma unroll
    for (int mb = 0; mb < 2; mb++) {
        const int ra = 32 * wm + 16 * mb + g;
#pragma unroll
        for (int j = 0; j < 4; j++) {
            const int c0 = 32 * wn + 8 * j + 2 * tig;
            const float bx = bs[c0], by = bs[c0 + 1];
            float x0 = tanh_fast(acc[mb][j].x + bx);
            float y0 = tanh_fast(acc[mb][j].y + by);
            float x1 = tanh_fast(acc[mb][j].z + bx);
            float y1 = tanh_fast(acc[mb][j].w + by);
            if (outS) {
                *(float2*)&outS[ra * 68 + c0]       = make_float2(tf32r(x0), tf32r(y0));
                *(float2*)&outS[(ra + 8) * 68 + c0] = make_float2(tf32r(x1), tf32r(y1));
            } else {
                *(float2*)&outG[(size_t)ra * 64 + c0]       = make_float2(x0, y0);
                *(float2*)&outG[(size_t)(ra + 8) * 64 + c0] = make_float2(x1, y1);
            }
        }
    }
}

__global__ void __launch_bounds__(256, 2) qkv_kernel(
    const float* __restrict__ x,
    const float* __restrict__ Wq1, const float* __restrict__ bq1,
    const float* __restrict__ Wq2, const float* __restrict__ bq2,
    const float* __restrict__ Wk1, const float* __restrict__ bk1,
    const float* __restrict__ Wk2, const float* __restrict__ bk2,
    const float* __restrict__ Wv1, const float* __restrict__ bv1,
    const float* __restrict__ Wv2, const float* __restrict__ bv2)
{
    extern __shared__ float sm[];
    float* xs = sm;                  // [128][68]
    float* zs = xs + 128 * 68;       // [128][68]
    float* Ws = zs + 128 * 68;       // [64][72]
    float* bs = Ws + 64 * 72;        // [64]

    const int hb = blockIdx.y;
    const int h = hb >> 3, b = hb & 7;
    const int s0 = blockIdx.x * 128;
    const int tid = threadIdx.x;
    const int w = tid >> 5, lane = tid & 31;
    const int wm = w >> 1, wn = w & 1, g = lane >> 2, tig = lane & 3;

    // ---- load x tile (coalesced along s), no pos-enc yet ----
    for (int i = tid; i < 128 * 64; i += 256) {
        int s = i & 127, d = i >> 7;
        xs[s * 68 + d] = x[((size_t)b * NE + (h * ND + d)) * NS + s0 + s];
    }
    __syncthreads();
    // ---- add pe (flat .view aliasing => contiguous in d); write exact fp32
    //      xh for the residual, and tf32-rounded values back to xs for MLPs ----
    const float* peb = g_pe + (size_t)h * (NS * ND);   // h*65536
    for (int i = tid; i < 2048; i += 256) {
        int s = i >> 4, c = (i & 15) * 4;
        float4 v = *(const float4*)&xs[s * 68 + c];
        float4 p = *(const float4*)&peb[(size_t)(s0 + s) * 64 + c];
        v.x += p.x; v.y += p.y; v.z += p.z; v.w += p.w;
        *(float4*)&g_xh[((size_t)hb * NS + s0 + s) * ND + c] = v;
        v.x = tf32r(v.x); v.y = tf32r(v.y);
        v.z = tf32r(v.z); v.w = tf32r(v.w);
        *(float4*)&xs[s * 68 + c] = v;
    }
    // (mma_layer's leading __syncthreads orders xs for all consumers)

    const size_t base = ((size_t)hb * NS + s0) * ND;
    mma_layer(xs, Wq1 + h * 4096, bq1 + h * 64, Ws, bs, zs, nullptr, wm, wn, g, tig, tid);
    mma_layer(zs, Wq2 + h * 4096, bq2 + h * 64, Ws, bs, nullptr, g_q + base, wm, wn, g, tig, tid);
    mma_layer(xs, Wk1 + h * 4096, bk1 + h * 64, Ws, bs, zs, nullptr, wm, wn, g, tig, tid);
    mma_layer(zs, Wk2 + h * 4096, bk2 + h * 64, Ws, bs, nullptr, g_k + base, wm, wn, g, tig, tid);
    mma_layer(xs, Wv1 + h * 4096, bv1 + h * 64, Ws, bs, zs, nullptr, wm, wn, g, tig, tid);
    mma_layer(zs, Wv2 + h * 4096, bv2 + h * 64, Ws, bs, nullptr, g_v + base, wm, wn, g, tig, tid);
}

// ============================================================================
// Kernel 2: flash attention per (h,b), 128 q-rows/block, tf32 mma.
// NO online max: q,k in [-1,1] => |s| <= 2, exp(s) safe in fp32.
// Row sums accumulate in registers; single cross-warp reduction at the end.
// K/V tiles double-buffered via cp.async (2 stages).
// ============================================================================
__global__ void __launch_bounds__(256, 1) attn_kernel()
{
    extern __shared__ float sm[];
    float* Qs   = sm;                    // [128][68]
    float* Ks   = Qs + 128 * 68;         // [2][64][68]
    float* Vs   = Ks + 2 * 64 * 68;      // [2][64][72]
    float* Ps   = Vs + 2 * 64 * 72;      // [128][68]
    float* ssum = Ps + 128 * 68;         // [2][128]

    const int hb = blockIdx.y;
    const int h = hb >> 3, b = hb & 7;
    const int q0 = blockIdx.x * 128;
    const int tid = threadIdx.x;
    const int w = tid >> 5, lane = tid & 31;
    const int wm = w >> 1, wn = w & 1, g = lane >> 2, tig = lane & 3;

    const float* kg0 = g_k + (size_t)hb * NS * ND;
    const float* vg0 = g_v + (size_t)hb * NS * ND;

    // ---- prefetch KV tile 0 into stage 0 ----
    {
        const int t = tid >> 2, c = (tid & 3) * 16;   // 64 rows x 4 chunks of 16 floats
#pragma unroll
        for (int u4 = 0; u4 < 4; u4++) {
            cpa16((uint32_t)__cvta_generic_to_shared(&Ks[t * 68 + c + 4 * u4]),
                  kg0 + (size_t)t * 64 + c + 4 * u4);
            cpa16((uint32_t)__cvta_generic_to_shared(&Vs[t * 72 + c + 4 * u4]),
                  vg0 + (size_t)t * 64 + c + 4 * u4);
        }
        CPA_COMMIT();
    }

    // ---- load Q tile (float4), scale by 1/sqrt(E)=1/32, round to tf32 ----
    const float* qg = g_q + ((size_t)hb * NS + q0) * ND;
    for (int i = tid; i < 2048; i += 256) {
        int r = i >> 4, c = (i & 15) * 4;
        float4 v = *(const float4*)&qg[(size_t)r * 64 + c];
        v.x = tf32r(v.x * (1.0f / 32.0f));
        v.y = tf32r(v.y * (1.0f / 32.0f));
        v.z = tf32r(v.z * (1.0f / 32.0f));
        v.w = tf32r(v.w * (1.0f / 32.0f));
        *(float4*)&Qs[r * 68 + c] = v;
    }
    __syncthreads();

    // ---- preload Q A-fragments: 2 row-blocks x 8 k-chunks ----
    uint32_t qa[2][8][4];
#pragma unroll
    for (int mb = 0; mb < 2; mb++) {
        const int ra = 32 * wm + 16 * mb + g;
#pragma unroll
        for (int kk = 0; kk < 8; kk++) {
            const int c = 8 * kk + tig;
            qa[mb][kk][0] = U(Qs[ra * 68 + c]);
            qa[mb][kk][1] = U(Qs[(ra + 8) * 68 + c]);
            qa[mb][kk][2] = U(Qs[ra * 68 + c + 4]);
            qa[mb][kk][3] = U(Qs[(ra + 8) * 68 + c + 4]);
        }
    }

    float l0[2] = {0.f, 0.f}, l1[2] = {0.f, 0.f};   // per-thread partial row sums
    float4 o[2][4];
#pragma unroll
    for (int mb = 0; mb < 2; mb++)
#pragma unroll
        for (int j = 0; j < 4; j++) o[mb][j] = make_float4(0.f, 0.f, 0.f, 0.f);

    for (int kt = 0; kt < 16; kt++) {
        const int st = kt & 1;
        float* Kb = Ks + st * (64 * 68);
        float* Vb = Vs + st * (64 * 72);

        // ---- prefetch tile kt+1 into the other stage ----
        if (kt + 1 < 16) {
            float* Kn = Ks + (st ^ 1) * (64 * 68);
            float* Vn = Vs + (st ^ 1) * (64 * 72);
            const float* kg = kg0 + (size_t)(kt + 1) * 64 * ND;
            const float* vg = vg0 + (size_t)(kt + 1) * 64 * ND;
            const int t = tid >> 2, c = (tid & 3) * 16;
#pragma unroll
            for (int u4 = 0; u4 < 4; u4++) {
                cpa16((uint32_t)__cvta_generic_to_shared(&Kn[t * 68 + c + 4 * u4]),
                      kg + (size_t)t * 64 + c + 4 * u4);
                cpa16((uint32_t)__cvta_generic_to_shared(&Vn[t * 72 + c + 4 * u4]),
                      vg + (size_t)t * 64 + c + 4 * u4);
            }
            CPA_COMMIT();
            asm volatile("cp.async.wait_group 1;");
        } else {
            asm volatile("cp.async.wait_group 0;");
        }
        __syncthreads();   // tile kt visible; prev compute done with this stage

        // ---- S = Q K^T : per row-block, rows x cols [32wn,+32) ----
        float4 sa[2][4];
#pragma unroll
        for (int mb = 0; mb < 2; mb++)
#pragma unroll
            for (int j = 0; j < 4; j++) sa[mb][j] = make_float4(0.f, 0.f, 0.f, 0.f);
#pragma unroll
        for (int kk = 0; kk < 8; kk++) {
#pragma unroll
            for (int j = 0; j < 4; j++) {
                const int n = 32 * wn + 8 * j + g;    // key index t
                uint32_t b0 = U(Kb[n * 68 + 8 * kk + tig]);
                uint32_t b1 = U(Kb[n * 68 + 8 * kk + tig + 4]);
                mma8(sa[0][j], qa[0][kk], b0, b1);
                mma8(sa[1][j], qa[1][kk], b0, b1);
            }
        }

        // ---- P = exp(S) (no max shift: |S| <= 2), accumulate sums in regs ----
#pragma unroll
        for (int mb = 0; mb < 2; mb++) {
            const int ra = 32 * wm + 16 * mb + g;
#pragma unroll
            for (int j = 0; j < 4; j++) {
                const int c0 = 32 * wn + 8 * j + 2 * tig;
                float px = __expf(sa[mb][j].x);
                float py = __expf(sa[mb][j].y);
                float pz = __expf(sa[mb][j].z);
                float pw = __expf(sa[mb][j].w);
                l0[mb] += px + py;
                l1[mb] += pz + pw;
                *(float2*)&Ps[ra * 68 + c0]       = make_float2(tf32r(px), tf32r(py));
                *(float2*)&Ps[(ra + 8) * 68 + c0] = make_float2(tf32r(pz), tf32r(pw));
            }
        }
        __syncthreads();   // Ps complete

        // ---- O += P V ----
#pragma unroll
        for (int kk = 0; kk < 8; kk++) {
            const int c = 8 * kk + tig;
            uint32_t pa[2][4];
#pragma unroll
            for (int mb = 0; mb < 2; mb++) {
                const int ra = 32 * wm + 16 * mb + g;
                pa[mb][0] = U(Ps[ra * 68 + c]);
                pa[mb][1] = U(Ps[(ra + 8) * 68 + c]);
                pa[mb][2] = U(Ps[ra * 68 + c + 4]);
                pa[mb][3] = U(Ps[(ra + 8) * 68 + c + 4]);
            }
#pragma unroll
            for (int j = 0; j < 4; j++) {
                const int n = 32 * wn + 8 * j + g;    // head-dim index d
                uint32_t b0 = U(Vb[(8 * kk + tig) * 72 + n]);
                uint32_t b1 = U(Vb[(8 * kk + tig + 4) * 72 + n]);
                mma8(o[0][j], pa[0], b0, b1);
                mma8(o[1][j], pa[1], b0, b1);
            }
        }
        __syncthreads();   // done reading Kb/Vb/Ps; safe to overwrite next iter
    }

    // ---- final row-sum reduction (once, not per tile) ----
#pragma unroll
    for (int mb = 0; mb < 2; mb++) {
#pragma unroll
        for (int off = 1; off <= 2; off <<= 1) {
            l0[mb] += __shfl_xor_sync(0xffffffffu, l0[mb], off);
            l1[mb] += __shfl_xor_sync(0xffffffffu, l1[mb], off);
        }
        const int ra = 32 * wm + 16 * mb + g;
        if (tig == 0) { ssum[wn * 128 + ra] = l0[mb]; ssum[wn * 128 + ra + 8] = l1[mb]; }
    }
    __syncthreads();
#pragma unroll
    for (int mb = 0; mb < 2; mb++) {
        const int ra = 32 * wm + 16 * mb + g;
        l0[mb] = ssum[ra] + ssum[128 + ra];
        l1[mb] = ssum[ra + 8] + ssum[128 + ra + 8];
    }

    // ---- epilogue: normalize, add fp32 residual, write y (b,s,e) ----
    const float* xg = g_xh + ((size_t)hb * NS + q0) * ND;
#pragma unroll
    for (int mb = 0; mb < 2; mb++) {
        const int ra = 32 * wm + 16 * mb + g;
        const float inv0 = 1.0f / l0[mb], inv1 = 1.0f / l1[mb];
#pragma unroll
        for (int j = 0; j < 4; j++) {
            const int c0 = 32 * wn + 8 * j + 2 * tig;
            float2 x0 = *(const float2*)&xg[(size_t)ra * 64 + c0];
            float2 x1 = *(const float2*)&xg[(size_t)(ra + 8) * 64 + c0];
            float2 y0 = make_float2(o[mb][j].x * inv0 + x0.x, o[mb][j].y * inv0 + x0.y);
            float2 y1 = make_float2(o[mb][j].z * inv1 + x1.x, o[mb][j].w * inv1 + x1.y);
            *(float2*)&g_y[((size_t)b * NS + q0 + ra) * NE + h * 64 + c0]     = y0;
            *(float2*)&g_y[((size_t)b * NS + q0 + ra + 8) * NE + h * 64 + c0] = y1;
        }
    }
}

// ============================================================================
// Kernel 3: per-(b,s) mean / rstd over E=1024
// ============================================================================
__global__ void stats_kernel()
{
    const int row = blockIdx.x;                // b*NS + s
    const int tid = threadIdx.x;               // 256
    const float4 v = ((const float4*)(g_y + (size_t)row * NE))[tid];
    float s  = (v.x + v.y) + (v.z + v.w);
    float s2 = (v.x * v.x + v.y * v.y) + (v.z * v.z + v.w * v.w);
#pragma unroll
    for (int off = 16; off; off >>= 1) {
        s  += __shfl_xor_sync(0xffffffffu, s,  off);
        s2 += __shfl_xor_sync(0xffffffffu, s2, off);
    }
    __shared__ float ws[8], ws2[8];
    if ((tid & 31) == 0) { ws[tid >> 5] = s; ws2[tid >> 5] = s2; }
    __syncthreads();
    if (tid == 0) {
        float a = 0.f, a2 = 0.f;
#pragma unroll
        for (int i = 0; i < 8; i++) { a += ws[i]; a2 += ws2[i]; }
        float mu = a * (1.0f / 1024.0f);
        float var = a2 * (1.0f / 1024.0f) - mu * mu;
        g_mu[row]   = mu;
        g_rstd[row] = rsqrtf(var + 1e-5f);
    }
}

// ============================================================================
// Kernel 4: layernorm affine + transpose (b,s,e) -> out (b,e,s)
// ============================================================================
__global__ void out_kernel(const float* __restrict__ gamma,
                           const float* __restrict__ beta,
                           float* __restrict__ out)
{
    __shared__ float tile[32][33];
    const int b  = blockIdx.z;
    const int e0 = blockIdx.y * 32;
    const int s0 = blockIdx.x * 32;
    const int tx = threadIdx.x, ty = threadIdx.y;   // 32 x 8

#pragma unroll
    for (int r = ty; r < 32; r += 8) {
        int s = s0 + r;
        float mu = g_mu[b * NS + s], rstd = g_rstd[b * NS + s];
        tile[r][tx] = (g_y[((size_t)b * NS + s) * NE + e0 + tx] - mu) * rstd;
    }
    __syncthreads();
#pragma unroll
    for (int r = ty; r < 32; r += 8) {
        int e = e0 + r;
        out[((size_t)b * NE + e) * NS + s0 + tx] = tile[tx][r] * gamma[e] + beta[e];
    }
}

// ============================================================================
extern "C" void kernel_launch(void* const* d_in, const int* in_sizes, int n_in,
                              void* d_out, int out_size)
{
    (void)in_sizes; (void)n_in; (void)out_size;
    const float* x    = (const float*)d_in[0];
    const float* Wq1  = (const float*)d_in[1];
    const float* bq1  = (const float*)d_in[2];
    const float* Wq2  = (const float*)d_in[3];
    const float* bq2  = (const float*)d_in[4];
    const float* Wk1  = (const float*)d_in[5];
    const float* bk1  = (const float*)d_in[6];
    const float* Wk2  = (const float*)d_in[7];
    const float* bk2  = (const float*)d_in[8];
    const float* Wv1  = (const float*)d_in[9];
    const float* bv1  = (const float*)d_in[10];
    const float* Wv2  = (const float*)d_in[11];
    const float* bv2  = (const float*)d_in[12];
    const float* gamma = (const float*)d_in[13];
    const float* beta  = (const float*)d_in[14];
    float* out = (float*)d_out;

    const int QKV_SMEM  = (128 * 68 * 2 + 64 * 72 + 64) * 4;  // 88320 B
    const int ATTN_SMEM = (128 * 68 + 2 * 64 * 68 + 2 * 64 * 72
                           + 128 * 68 + 2 * 128) * 4;         // 142336 B
    cudaFuncSetAttribute(qkv_kernel,  cudaFuncAttributeMaxDynamicSharedMemorySize, QKV_SMEM);
    cudaFuncSetAttribute(attn_kernel, cudaFuncAttributeMaxDynamicSharedMemorySize, ATTN_SMEM);

    pe_kernel<<<(NS * NE / 2) / 256, 256>>>();
    qkv_kernel<<<dim3(NS / 128, NHB), 256, QKV_SMEM>>>(
        x, Wq1, bq1, Wq2, bq2, Wk1, bk1, Wk2, bk2, Wv1, bv1, Wv2, bv2);
    attn_kernel<<<dim3(NS / 128, NHB), 256, ATTN_SMEM>>>();
    stats_kernel<<<NB * NS, 256>>>();
    out_kernel<<<dim3(NS / 32, NE / 32, NB), dim3(32, 8)>>>(gamma, beta, out);
}

// round 13
// speedup vs baseline: 1.7898x; 1.7898x over previous
#include <cuda_runtime.h>
#include <cuda_bf16.h>
#include <math.h>
#include <stdint.h>

#define NB 8
#define NH 16
#define ND 64
#define NS 1024
#define NE 1024
#define NHB 128   // NH*NB

// ---- scratch (device globals; no allocations allowed) ----
__device__ float g_pe[NS * NE];               // (L,E) positional encoding table
__device__ float g_xh[NHB * NS * ND];         // (h,b,s,d) + pos-enc, fp32 residual
__device__ __nv_bfloat16 g_qb[NHB * NS * ND]; // q/32, bf16, [hb][s][d]
__device__ __nv_bfloat16 g_kb[NHB * NS * ND]; // k, bf16, [hb][s][d]
__device__ __nv_bfloat16 g_vT[NHB * ND * NS]; // v, bf16, TRANSPOSED [hb][d][s]
__device__ float g_y [NB * NS * NE];          // (b,s,e) pre-layernorm
__device__ float g_mu  [NB * NS];
__device__ float g_rstd[NB * NS];

// ---------------------------------------------------------------------------
// helpers
// ---------------------------------------------------------------------------
__device__ __forceinline__ float tf32r(float f) {
    uint32_t u;
    asm("cvt.rna.tf32.f32 %0, %1;" : "=r"(u) : "f"(f));
    return __uint_as_float(u);
}
__device__ __forceinline__ float tanh_fast(float x) {
    float y;
    asm("tanh.approx.f32 %0, %1;" : "=f"(y) : "f"(x));
    return y;
}
// pack two floats to bf16x2: lo -> low half, hi -> high half
__device__ __forceinline__ uint32_t bf2(float lo, float hi) {
    uint32_t r;
    asm("cvt.rn.bf16x2.f32 %0, %1, %2;" : "=r"(r) : "f"(hi), "f"(lo));
    return r;
}
// tf32: D += A(16x8) * B(8x8)
__device__ __forceinline__ void mma8(float4& d, const uint32_t a[4],
                                     uint32_t b0, uint32_t b1) {
    asm("mma.sync.aligned.m16n8k8.row.col.f32.tf32.tf32.f32 "
        "{%0,%1,%2,%3}, {%4,%5,%6,%7}, {%8,%9}, {%0,%1,%2,%3};"
        : "+f"(d.x), "+f"(d.y), "+f"(d.z), "+f"(d.w)
        : "r"(a[0]), "r"(a[1]), "r"(a[2]), "r"(a[3]), "r"(b0), "r"(b1));
}
// bf16: D += A(16x16) * B(16x8)
__device__ __forceinline__ void mma16(float4& d, const uint32_t a[4],
                                      uint32_t b0, uint32_t b1) {
    asm("mma.sync.aligned.m16n8k16.row.col.f32.bf16.bf16.f32 "
        "{%0,%1,%2,%3}, {%4,%5,%6,%7}, {%8,%9}, {%0,%1,%2,%3};"
        : "+f"(d.x), "+f"(d.y), "+f"(d.z), "+f"(d.w)
        : "r"(a[0]), "r"(a[1]), "r"(a[2]), "r"(a[3]), "r"(b0), "r"(b1));
}
__device__ __forceinline__ void cpa16(uint32_t smem_addr, const void* gptr) {
    asm volatile("cp.async.cg.shared.global [%0], [%1], 16;"
                 :: "r"(smem_addr), "l"(gptr));
}
#define CPA_COMMIT() asm volatile("cp.async.commit_group;")
#define U(x) __float_as_uint(x)

// ============================================================================
// Kernel 0: precompute (L,E) pos-enc table.
// ============================================================================
__global__ void pe_kernel()
{
    const int i = blockIdx.x * blockDim.x + threadIdx.x;   // 0 .. 524287
    const int l = i >> 9;
    const int e = (i & 511) * 2;
    const float ln_factor = 0.0089944730195079f;   // log(10000)/1024
    float dv  = expf(-(float)e * ln_factor);
    float ang = (float)l * dv;
    float s, c;
    sincosf(ang, &s, &c);
    *(float2*)&g_pe[l * NE + e] = make_float2(s, c);
}

// ============================================================================
// Kernel 1: xh = reshape(x)+pe ; q/k/v via per-head 2-layer tanh MLP (tf32 mma)
// q,k written bf16 (q pre-scaled 1/32); v written bf16 TRANSPOSED [d][s].
// ============================================================================
__device__ __forceinline__ void mma_layer(
    const float* As,                     // smem [128][68], tf32 values
    const float* __restrict__ Wg,        // global [64][64]
    const float* __restrict__ bg,        // global [64]
    float* Ws, float* bs,                // smem staging [64][72], [64]
    float* outS,                         // smem [128][68] (tf32) or nullptr
    __nv_bfloat16* outGb, float oscale,  // bf16 global [s][d] or nullptr
    int wm, int wn, int g, int tig, int tid)
{
    __syncthreads();
    for (int i = tid; i < 1024; i += 256) {
        int r = i >> 4, c = (i & 15) * 4;
        float4 wv = *(const float4*)&Wg[r * 64 + c];
        wv.x = tf32r(wv.x); wv.y = tf32r(wv.y);
        wv.z = tf32r(wv.z); wv.w = tf32r(wv.w);
        *(float4*)&Ws[r * 72 + c] = wv;
    }
    if (tid < 64) bs[tid] = bg[tid];
    __syncthreads();

    float4 acc[2][4];
#pragma unroll
    for (int mb = 0; mb < 2; mb++)
#pragma unroll
        for (int j = 0; j < 4; j++) acc[mb][j] = make_float4(0.f, 0.f, 0.f, 0.f);

#pragma unroll
    for (int kk = 0; kk < 8; kk++) {
        const int c = 8 * kk + tig;
        uint32_t a[2][4];
#pragma unroll
        for (int mb = 0; mb < 2; mb++) {
            const int ra = 32 * wm + 16 * mb + g;
            a[mb][0] = U(As[ra * 68 + c]);
            a[mb][1] = U(As[(ra + 8) * 68 + c]);
            a[mb][2] = U(As[ra * 68 + c + 4]);
            a[mb][3] = U(As[(ra + 8) * 68 + c + 4]);
        }
#pragma unroll
        for (int j = 0; j < 4; j++) {
            const int n = 32 * wn + 8 * j + g;
            uint32_t b0 = U(Ws[(8 * kk + tig) * 72 + n]);
            uint32_t b1 = U(Ws[(8 * kk + tig + 4) * 72 + n]);
            mma8(acc[0][j], a[0], b0, b1);
            mma8(acc[1][j], a[1], b0, b1);
        }
    }
#pragma unroll
    for (int mb = 0; mb < 2; mb++) {
        const int ra = 32 * wm + 16 * mb + g;
#pragma unroll
        for (int j = 0; j < 4; j++) {
            const int c0 = 32 * wn + 8 * j + 2 * tig;
            const float bx = bs[c0], by = bs[c0 + 1];
            float x0 = tanh_fast(acc[mb][j].x + bx);
            float y0 = tanh_fast(acc[mb][j].y + by);
            float x1 = tanh_fast(acc[mb][j].z + bx);
            float y1 = tanh_fast(acc[mb][j].w + by);
            if (outS) {
                *(float2*)&outS[ra * 68 + c0]       = make_float2(tf32r(x0), tf32r(y0));
                *(float2*)&outS[(ra + 8) * 68 + c0] = make_float2(tf32r(x1), tf32r(y1));
            } else {
                *(uint32_t*)&outGb[(size_t)ra * 64 + c0] =
                    bf2(x0 * oscale, y0 * oscale);
                *(uint32_t*)&outGb[(size_t)(ra + 8) * 64 + c0] =
                    bf2(x1 * oscale, y1 * oscale);
            }
        }
    }
}

__global__ void __launch_bounds__(256, 2) qkv_kernel(
    const float* __restrict__ x,
    const float* __restrict__ Wq1, const float* __restrict__ bq1,
    const float* __restrict__ Wq2, const float* __restrict__ bq2,
    const float* __restrict__ Wk1, const float* __restrict__ bk1,
    const float* __restrict__ Wk2, const float* __restrict__ bk2,
    const float* __restrict__ Wv1, const float* __restrict__ bv1,
    const float* __restrict__ Wv2, const float* __restrict__ bv2)
{
    extern __shared__ float sm[];
    float* xs = sm;                  // [128][68]
    float* zs = xs + 128 * 68;       // [128][68]
    float* Ws = zs + 128 * 68;       // [64][72]
    float* bs = Ws + 64 * 72;        // [64]

    const int hb = blockIdx.y;
    const int h = hb >> 3, b = hb & 7;
    const int s0 = blockIdx.x * 128;
    const int tid = threadIdx.x;
    const int w = tid >> 5, lane = tid & 31;
    const int wm = w >> 1, wn = w & 1, g = lane >> 2, tig = lane & 3;

    // ---- load x tile (coalesced along s) ----
    for (int i = tid; i < 128 * 64; i += 256) {
        int s = i & 127, d = i >> 7;
        xs[s * 68 + d] = x[((size_t)b * NE + (h * ND + d)) * NS + s0 + s];
    }
    __syncthreads();
    // ---- add pe; write fp32 xh; tf32-round xs for the MLPs ----
    const float* peb = g_pe + (size_t)h * (NS * ND);
    for (int i = tid; i < 2048; i += 256) {
        int s = i >> 4, c = (i & 15) * 4;
        float4 v = *(const float4*)&xs[s * 68 + c];
        float4 p = *(const float4*)&peb[(size_t)(s0 + s) * 64 + c];
        v.x += p.x; v.y += p.y; v.z += p.z; v.w += p.w;
        *(float4*)&g_xh[((size_t)hb * NS + s0 + s) * ND + c] = v;
        v.x = tf32r(v.x); v.y = tf32r(v.y);
        v.z = tf32r(v.z); v.w = tf32r(v.w);
        *(float4*)&xs[s * 68 + c] = v;
    }

    const size_t base = ((size_t)hb * NS + s0) * ND;
    // Q: tanh MLP, output bf16 pre-scaled by 1/sqrt(E)=1/32
    mma_layer(xs, Wq1 + h * 4096, bq1 + h * 64, Ws, bs, zs, nullptr, 1.f, wm, wn, g, tig, tid);
    mma_layer(zs, Wq2 + h * 4096, bq2 + h * 64, Ws, bs, nullptr, g_qb + base, 1.0f / 32.0f, wm, wn, g, tig, tid);
    // K: bf16
    mma_layer(xs, Wk1 + h * 4096, bk1 + h * 64, Ws, bs, zs, nullptr, 1.f, wm, wn, g, tig, tid);
    mma_layer(zs, Wk2 + h * 4096, bk2 + h * 64, Ws, bs, nullptr, g_kb + base, 1.0f, wm, wn, g, tig, tid);
    // V: layer1 xs->zs, layer2 zs->xs (xs free now), then transpose to g_vT
    mma_layer(xs, Wv1 + h * 4096, bv1 + h * 64, Ws, bs, zs, nullptr, 1.f, wm, wn, g, tig, tid);
    mma_layer(zs, Wv2 + h * 4096, bv2 + h * 64, Ws, bs, xs, nullptr, 1.f, wm, wn, g, tig, tid);
    __syncthreads();

    // ---- transpose v: xs [128 s][68] -> g_vT bf16 [hb][d][s] ----
    {
        const int d  = tid >> 2;           // 0..63
        const int sc = (tid & 3) * 32;     // s-chunk base
        const size_t rowb = ((size_t)(hb * ND + d)) * NS + s0 + sc;
#pragma unroll
        for (int i2 = 0; i2 < 32; i2 += 2) {
            float v0 = xs[(sc + i2) * 68 + d];
            float v1 = xs[(sc + i2 + 1) * 68 + d];
            *(uint32_t*)&g_vT[rowb + i2] = bf2(v0, v1);
        }
    }
}

// ============================================================================
// Kernel 2: flash attention per (h,b), 128 q-rows/block, bf16 m16n8k16 mma.
// Each warp owns 16 FULL rows (s) x all 64 keys/dims: P stays in registers.
// No online max (|s|<=2). 1 barrier/tile. K/V double-buffered cp.async. occ 2.
// ============================================================================
__global__ void __launch_bounds__(256, 2) attn_kernel()
{
    extern __shared__ __align__(16) char smc[];
    const int STAGE = 64 * 144;            // 64 rows x 72 bf16 (144 B)
    char* Kb0 = smc;                       // [2][64][144B]
    char* Vb0 = smc + 2 * STAGE;           // [2][64][144B]

    const int hb = blockIdx.y;
    const int h = hb >> 3, b = hb & 7;
    const int q0 = blockIdx.x * 128;
    const int tid = threadIdx.x;
    const int w = tid >> 5, lane = tid & 31;
    const int g = lane >> 2, tig = lane & 3;
    const int r0 = 16 * w + g;             // this thread's first row

    const char* kg  = (const char*)(g_kb + (size_t)hb * NS * ND);  // [s][d] bf16
    const char* vtg = (const char*)(g_vT + (size_t)hb * ND * NS);  // [d][s] bf16

    // ---- prefetch tile 0 into stage 0 (K: rows t, V: rows d; 128B/row) ----
    {
        int c0 = tid, c1 = tid + 256;
        int t0 = c0 >> 3, o0 = (c0 & 7) * 16;
        int t1 = c1 >> 3, o1 = (c1 & 7) * 16;
        cpa16((uint32_t)__cvta_generic_to_shared(Kb0 + t0 * 144 + o0),
              kg + (size_t)t0 * 128 + o0);
        cpa16((uint32_t)__cvta_generic_to_shared(Kb0 + t1 * 144 + o1),
              kg + (size_t)t1 * 128 + o1);
        cpa16((uint32_t)__cvta_generic_to_shared(Vb0 + t0 * 144 + o0),
              vtg + (size_t)t0 * 2048 + o0);
        cpa16((uint32_t)__cvta_generic_to_shared(Vb0 + t1 * 144 + o1),
              vtg + (size_t)t1 * 2048 + o1);
        CPA_COMMIT();
    }

    // ---- load Q fragments directly from gmem (bf16, pre-scaled) ----
    const char* qrow0 = (const char*)(g_qb + ((size_t)hb * NS + q0 + r0) * 64);
    const char* qrow1 = qrow0 + 8 * 128;
    uint32_t qa[4][4];
#pragma unroll
    for (int kk = 0; kk < 4; kk++) {
        qa[kk][0] = *(const uint32_t*)(qrow0 + (16 * kk + 2 * tig) * 2);
        qa[kk][1] = *(const uint32_t*)(qrow1 + (16 * kk + 2 * tig) * 2);
        qa[kk][2] = *(const uint32_t*)(qrow0 + (16 * kk + 2 * tig + 8) * 2);
        qa[kk][3] = *(const uint32_t*)(qrow1 + (16 * kk + 2 * tig + 8) * 2);
    }

    float l0 = 0.f, l1 = 0.f;
    float4 o[8];
#pragma unroll
    for (int j = 0; j < 8; j++) o[j] = make_float4(0.f, 0.f, 0.f, 0.f);

    for (int kt = 0; kt < 16; kt++) {
        const int st = kt & 1;
        asm volatile("cp.async.wait_group 0;");
        __syncthreads();   // tile kt visible; all warps done with stage st^1

        if (kt + 1 < 16) {   // prefetch kt+1 into st^1
            char* Kn = Kb0 + (st ^ 1) * STAGE;
            char* Vn = Vb0 + (st ^ 1) * STAGE;
            int c0 = tid, c1 = tid + 256;
            int t0 = c0 >> 3, o0 = (c0 & 7) * 16;
            int t1 = c1 >> 3, o1 = (c1 & 7) * 16;
            size_t kt1 = (size_t)(kt + 1);
            cpa16((uint32_t)__cvta_generic_to_shared(Kn + t0 * 144 + o0),
                  kg + (kt1 * 64 + t0) * 128 + o0);
            cpa16((uint32_t)__cvta_generic_to_shared(Kn + t1 * 144 + o1),
                  kg + (kt1 * 64 + t1) * 128 + o1);
            cpa16((uint32_t)__cvta_generic_to_shared(Vn + t0 * 144 + o0),
                  vtg + (size_t)t0 * 2048 + kt1 * 128 + o0);
            cpa16((uint32_t)__cvta_generic_to_shared(Vn + t1 * 144 + o1),
                  vtg + (size_t)t1 * 2048 + kt1 * 128 + o1);
            CPA_COMMIT();
        }

        const char* Kb = Kb0 + st * STAGE;
        const char* Vb = Vb0 + st * STAGE;

        // ---- S = Q K^T : 16 rows x 64 keys per warp ----
        float4 sa[8];
#pragma unroll
        for (int j = 0; j < 8; j++) sa[j] = make_float4(0.f, 0.f, 0.f, 0.f);
#pragma unroll
        for (int kk = 0; kk < 4; kk++) {
#pragma unroll
            for (int j = 0; j < 8; j++) {
                const char* krow = Kb + (8 * j + g) * 144;
                uint32_t b0 = *(const uint32_t*)(krow + (16 * kk + 2 * tig) * 2);
                uint32_t b1 = *(const uint32_t*)(krow + (16 * kk + 2 * tig + 8) * 2);
                mma16(sa[j], qa[kk], b0, b1);
            }
        }

        // ---- P = exp(S) in registers (A-frag layout), partial row sums ----
        uint32_t pa[4][4];
#pragma unroll
        for (int kk2 = 0; kk2 < 4; kk2++) {
            float4 sA = sa[2 * kk2], sB = sa[2 * kk2 + 1];
            float e0 = __expf(sA.x), e1 = __expf(sA.y);
            float e2 = __expf(sA.z), e3 = __expf(sA.w);
            float f0 = __expf(sB.x), f1 = __expf(sB.y);
            float f2 = __expf(sB.z), f3 = __expf(sB.w);
            l0 += (e0 + e1) + (f0 + f1);
            l1 += (e2 + e3) + (f2 + f3);
            pa[kk2][0] = bf2(e0, e1);
            pa[kk2][1] = bf2(e2, e3);
            pa[kk2][2] = bf2(f0, f1);
            pa[kk2][3] = bf2(f2, f3);
        }

        // ---- O += P V : 16 rows x 64 dims per warp ----
#pragma unroll
        for (int kk2 = 0; kk2 < 4; kk2++) {
#pragma unroll
            for (int j = 0; j < 8; j++) {
                const char* vrow = Vb + (8 * j + g) * 144;
                uint32_t b0 = *(const uint32_t*)(vrow + (16 * kk2 + 2 * tig) * 2);
                uint32_t b1 = *(const uint32_t*)(vrow + (16 * kk2 + 2 * tig + 8) * 2);
                mma16(o[j], pa[kk2], b0, b1);
            }
        }
    }

    // ---- complete row sums (within tig group of 4 lanes; rows are warp-local) ----
    l0 += __shfl_xor_sync(0xffffffffu, l0, 1);
    l0 += __shfl_xor_sync(0xffffffffu, l0, 2);
    l1 += __shfl_xor_sync(0xffffffffu, l1, 1);
    l1 += __shfl_xor_sync(0xffffffffu, l1, 2);
    const float inv0 = 1.0f / l0, inv1 = 1.0f / l1;

    // ---- epilogue: normalize, add fp32 residual, write y (b,s,e) ----
    const float* xg = g_xh + ((size_t)hb * NS + q0) * ND;
#pragma unroll
    for (int j = 0; j < 8; j++) {
        const int c0 = 8 * j + 2 * tig;
        float2 x0 = *(const float2*)&xg[(size_t)r0 * 64 + c0];
        float2 x1 = *(const float2*)&xg[(size_t)(r0 + 8) * 64 + c0];
        float2 y0 = make_float2(o[j].x * inv0 + x0.x, o[j].y * inv0 + x0.y);
        float2 y1 = make_float2(o[j].z * inv1 + x1.x, o[j].w * inv1 + x1.y);
        *(float2*)&g_y[((size_t)b * NS + q0 + r0) * NE + h * 64 + c0]     = y0;
        *(float2*)&g_y[((size_t)b * NS + q0 + r0 + 8) * NE + h * 64 + c0] = y1;
    }
}

// ============================================================================
// Kernel 3: per-(b,s) mean / rstd over E=1024
// ============================================================================
__global__ void stats_kernel()
{
    const int row = blockIdx.x;
    const int tid = threadIdx.x;               // 256
    const float4 v = ((const float4*)(g_y + (size_t)row * NE))[tid];
    float s  = (v.x + v.y) + (v.z + v.w);
    float s2 = (v.x * v.x + v.y * v.y) + (v.z * v.z + v.w * v.w);
#pragma unroll
    for (int off = 16; off; off >>= 1) {
        s  += __shfl_xor_sync(0xffffffffu, s,  off);
        s2 += __shfl_xor_sync(0xffffffffu, s2, off);
    }
    __shared__ float ws[8], ws2[8];
    if ((tid & 31) == 0) { ws[tid >> 5] = s; ws2[tid >> 5] = s2; }
    __syncthreads();
    if (tid == 0) {
        float a = 0.f, a2 = 0.f;
#pragma unroll
        for (int i = 0; i < 8; i++) { a += ws[i]; a2 += ws2[i]; }
        float mu = a * (1.0f / 1024.0f);
        float var = a2 * (1.0f / 1024.0f) - mu * mu;
        g_mu[row]   = mu;
        g_rstd[row] = rsqrtf(var + 1e-5f);
    }
}

// ============================================================================
// Kernel 4: layernorm affine + transpose (b,s,e) -> out (b,e,s)
// ============================================================================
__global__ void out_kernel(const float* __restrict__ gamma,
                           const float* __restrict__ beta,
                           float* __restrict__ out)
{
    __shared__ float tile[32][33];
    const int b  = blockIdx.z;
    const int e0 = blockIdx.y * 32;
    const int s0 = blockIdx.x * 32;
    const int tx = threadIdx.x, ty = threadIdx.y;   // 32 x 8

#pragma unroll
    for (int r = ty; r < 32; r += 8) {
        int s = s0 + r;
        float mu = g_mu[b * NS + s], rstd = g_rstd[b * NS + s];
        tile[r][tx] = (g_y[((size_t)b * NS + s) * NE + e0 + tx] - mu) * rstd;
    }
    __syncthreads();
#pragma unroll
    for (int r = ty; r < 32; r += 8) {
        int e = e0 + r;
        out[((size_t)b * NE + e) * NS + s0 + tx] = tile[tx][r] * gamma[e] + beta[e];
    }
}

// ============================================================================
extern "C" void kernel_launch(void* const* d_in, const int* in_sizes, int n_in,
                              void* d_out, int out_size)
{
    (void)in_sizes; (void)n_in; (void)out_size;
    const float* x    = (const float*)d_in[0];
    const float* Wq1  = (const float*)d_in[1];
    const float* bq1  = (const float*)d_in[2];
    const float* Wq2  = (const float*)d_in[3];
    const float* bq2  = (const float*)d_in[4];
    const float* Wk1  = (const float*)d_in[5];
    const float* bk1  = (const float*)d_in[6];
    const float* Wk2  = (const float*)d_in[7];
    const float* bk2  = (const float*)d_in[8];
    const float* Wv1  = (const float*)d_in[9];
    const float* bv1  = (const float*)d_in[10];
    const float* Wv2  = (const float*)d_in[11];
    const float* bv2  = (const float*)d_in[12];
    const float* gamma = (const float*)d_in[13];
    const float* beta  = (const float*)d_in[14];
    float* out = (float*)d_out;

    const int QKV_SMEM  = (128 * 68 * 2 + 64 * 72 + 64) * 4;  // 88320 B
    const int ATTN_SMEM = 4 * 64 * 144;                       // 36864 B
    cudaFuncSetAttribute(qkv_kernel,  cudaFuncAttributeMaxDynamicSharedMemorySize, QKV_SMEM);
    cudaFuncSetAttribute(attn_kernel, cudaFuncAttributeMaxDynamicSharedMemorySize, ATTN_SMEM);

    pe_kernel<<<(NS * NE / 2) / 256, 256>>>();
    qkv_kernel<<<dim3(NS / 128, NHB), 256, QKV_SMEM>>>(
        x, Wq1, bq1, Wq2, bq2, Wk1, bk1, Wk2, bk2, Wv1, bv1, Wv2, bv2);
    attn_kernel<<<dim3(NS / 128, NHB), 256, ATTN_SMEM>>>();
    stats_kernel<<<NB * NS, 256>>>();
    out_kernel<<<dim3(NS / 32, NE / 32, NB), dim3(32, 8)>>>(gamma, beta, out);
}